// round 11
// baseline (speedup 1.0000x reference)
#include <cuda_runtime.h>
#include <cuda_bf16.h>
#include <cstdint>

// ============================================================================
// SSGP folded: f[n,i] = sum_{b<1024} cos(sim[n,b]+phi_b) * mat[b,i]
// via mma.sync.m16n8k16 bf16, split precision (drop lo*lo terms).
// Occupancy build: 32-row blocks, grid 256, 2 CTAs/SM (4 warps/SMSP).
// Warp = 16 rows x 16-basis quarter; partials over b combined in smem.
// ============================================================================

__device__ float g_phi[1024];
__device__ __nv_bfloat16 g_qs[16][64][128];  // [chunk][b][ qh(64) | ql(64) ]
__device__ __nv_bfloat16 g_ms[16][64][128];  // [chunk][b][ mh(64) | ml(64) ]

// ---------------- prep ----------------
__global__ void ssgp_prep(const float* __restrict__ eps,
                          const float* __restrict__ lam,
                          const float* __restrict__ eta,
                          const float* __restrict__ w) {
    int idx = blockIdx.x * blockDim.x + threadIdx.x;  // 65536
    int b = idx >> 6, j = idx & 63;
    int ch = b >> 6, bp = b & 63;
    float S = w[b] + w[b + 1024];
    float C = w[2048 + b] - w[3072 + b];
    float R = sqrtf(S * S + C * C);
    if (j == 0) g_phi[b] = atan2f(S, C);

    float e2 = eta[0] * eta[0];
    float q = eps[b * 64 + j] / lam[j];
    __nv_bfloat16 qh = __float2bfloat16_rn(q);
    __nv_bfloat16 ql = __float2bfloat16_rn(q - __bfloat162float(qh));
    g_qs[ch][bp][j]      = qh;
    g_qs[ch][bp][64 + j] = ql;

    float m;
    if (j < 32) m = R * (eps[b * 64 + j + 32] / lam[j + 32]);
    else        m = -R * (eps[b * 64 + j - 32] / lam[j - 32] + e2 * q);
    __nv_bfloat16 mh = __float2bfloat16_rn(m);
    __nv_bfloat16 ml = __float2bfloat16_rn(m - __bfloat162float(mh));
    g_ms[ch][bp][j]      = mh;
    g_ms[ch][bp][64 + j] = ml;
}

// ---------------- asm helpers ----------------
__device__ __forceinline__ uint32_t smem_u32(const void* p) {
    uint32_t a;
    asm("{ .reg .u64 t; cvta.to.shared.u64 t, %1; cvt.u32.u64 %0, t; }" : "=r"(a) : "l"(p));
    return a;
}
__device__ __forceinline__ void mma16816(float* d, const uint32_t* a, const uint32_t* b) {
    asm volatile(
        "mma.sync.aligned.m16n8k16.row.col.f32.bf16.bf16.f32 "
        "{%0,%1,%2,%3}, {%4,%5,%6,%7}, {%8,%9}, {%0,%1,%2,%3};"
        : "+f"(d[0]), "+f"(d[1]), "+f"(d[2]), "+f"(d[3])
        : "r"(a[0]), "r"(a[1]), "r"(a[2]), "r"(a[3]), "r"(b[0]), "r"(b[1]));
}
__device__ __forceinline__ void ldsm_x4(uint32_t* r, uint32_t addr) {
    asm volatile("ldmatrix.sync.aligned.m8n8.x4.shared.b16 {%0,%1,%2,%3}, [%4];"
                 : "=r"(r[0]), "=r"(r[1]), "=r"(r[2]), "=r"(r[3]) : "r"(addr));
}
__device__ __forceinline__ void ldsm_x4t(uint32_t* r, uint32_t addr) {
    asm volatile("ldmatrix.sync.aligned.m8n8.x4.trans.shared.b16 {%0,%1,%2,%3}, [%4];"
                 : "=r"(r[0]), "=r"(r[1]), "=r"(r[2]), "=r"(r[3]) : "r"(addr));
}
__device__ __forceinline__ void cpa16(uint32_t s, const void* g) {
    asm volatile("cp.async.cg.shared.global [%0], [%1], 16;" :: "r"(s), "l"(g));
}
__device__ __forceinline__ uint32_t pack_bf2(float lo, float hi) {
    __nv_bfloat162 v(__float2bfloat16_rn(lo), __float2bfloat16_rn(hi));
    return *(uint32_t*)&v;
}

// ---------------- smem layout (per CTA: 82432 B) ----------------
#define ROWB 272                        // 128 bf16 + 16B pad
#define SX_OFF 0                        // x tile: 32 rows x ROWB = 8704
#define QBUF(d) (8704 + (d) * 17408)    // q chunk dbuf
#define MBUF(d) (43520 + (d) * 17408)   // m chunk dbuf
#define PHI_OFF 78336                   // 1024 f32
#define SMEM_BYTES 82432

__device__ __forceinline__ void pf_chunk(uint32_t sb, int gc, int d, int tid) {
    uint32_t qdst = sb + QBUF(d);
    uint32_t mdst = sb + MBUF(d);
    const char* qsrc = (const char*)g_qs[gc];
    const char* msrc = (const char*)g_ms[gc];
#pragma unroll
    for (int r = 0; r < 4; r++) {
        int e = tid + r * 256;          // 1024 x 16B units per table
        uint32_t off = (uint32_t)(e >> 4) * ROWB + (uint32_t)(e & 15) * 16;
        cpa16(qdst + off, qsrc + e * 16);
        cpa16(mdst + off, msrc + e * 16);
    }
}

// ---------------- main ----------------
__global__ void __launch_bounds__(256, 2)
ssgp_hmma(const float* __restrict__ x, float* __restrict__ out) {
    extern __shared__ char smem[];
    const uint32_t sb = smem_u32(smem);
    const int tid = threadIdx.x, lane = tid & 31, w = tid >> 5;
    const int rg = w >> 2, qt = w & 3;         // row-group (16 rows), b-quarter
    const int row0 = blockIdx.x * 32;

    // prefetch phi + first two chunks
    cpa16(sb + PHI_OFF + tid * 16, (const char*)g_phi + tid * 16);
    pf_chunk(sb, 0, 0, tid);
    asm volatile("cp.async.commit_group;");
    pf_chunk(sb, 1, 1, tid);
    asm volatile("cp.async.commit_group;");

    // stage x tile: 32 rows x [xh(64)|xl(64)] bf16
#pragma unroll
    for (int k = 0; k < 2; k++) {
        int e = tid + k * 256;                 // 512 float4s
        int row = e >> 4, c4 = e & 15;
        float4 v = *(const float4*)&x[(row0 + row) * 64 + c4 * 4];
        float vh[4] = {v.x, v.y, v.z, v.w};
        uint32_t hp[2], lp[2];
#pragma unroll
        for (int p = 0; p < 2; p++) {
            float a = vh[2 * p], b = vh[2 * p + 1];
            float ah_ = __bfloat162float(__float2bfloat16_rn(a));
            float bh_ = __bfloat162float(__float2bfloat16_rn(b));
            hp[p] = pack_bf2(a, b);
            lp[p] = pack_bf2(a - ah_, b - bh_);
        }
        char* rp = smem + SX_OFF + row * ROWB;
        *(uint2*)(rp + c4 * 8)       = make_uint2(hp[0], hp[1]);
        *(uint2*)(rp + 128 + c4 * 8) = make_uint2(lp[0], lp[1]);
    }
    __syncthreads();

    // persistent x A-fragments [hi/lo][jb][4] for rows rg*16..+15
    uint32_t xa[2][4][4];
#pragma unroll
    for (int s = 0; s < 2; s++)
#pragma unroll
        for (int jb = 0; jb < 4; jb++) {
            uint32_t addr = sb + SX_OFF + (uint32_t)(rg * 16 + (lane & 15)) * ROWB
                          + (uint32_t)(s * 64 + jb * 16 + ((lane >> 4) & 1) * 8) * 2;
            ldsm_x4(xa[s][jb], addr);
        }

    float f[8][4];
#pragma unroll
    for (int it = 0; it < 8; it++)
#pragma unroll
        for (int r = 0; r < 4; r++) f[it][r] = 0.f;

    const float* sphi = (const float*)(smem + PHI_OFF);

    for (int cc = 0; cc < 16; ++cc) {
        asm volatile("cp.async.wait_group 1;" ::: "memory");
        __syncthreads();
        const uint32_t qb = sb + QBUF(cc & 1);
        const uint32_t mb = sb + MBUF(cc & 1);

        // ---- GEMM1: sim[16 x 16] = x . q^T (quarter qt), K=192 split ----
        float s[2][4];
#pragma unroll
        for (int nt = 0; nt < 2; nt++) {
            uint32_t base = qb + (uint32_t)(qt * 16 + nt * 8 + (lane & 7)) * ROWB
                          + (uint32_t)((lane >> 3) * 8) * 2;
            uint32_t bh[4][2], bl[4][2], r[4];
            ldsm_x4(r, base);                 // k 0..31 hi
            bh[0][0] = r[0]; bh[0][1] = r[1]; bh[1][0] = r[2]; bh[1][1] = r[3];
            ldsm_x4(r, base + 32 * 2);        // k 32..63 hi
            bh[2][0] = r[0]; bh[2][1] = r[1]; bh[3][0] = r[2]; bh[3][1] = r[3];
            ldsm_x4(r, base + 64 * 2);        // k 0..31 lo
            bl[0][0] = r[0]; bl[0][1] = r[1]; bl[1][0] = r[2]; bl[1][1] = r[3];
            ldsm_x4(r, base + 96 * 2);        // k 32..63 lo
            bl[2][0] = r[0]; bl[2][1] = r[1]; bl[3][0] = r[2]; bl[3][1] = r[3];
#pragma unroll
            for (int r4 = 0; r4 < 4; r4++) s[nt][r4] = 0.f;
#pragma unroll
            for (int jb = 0; jb < 4; jb++) mma16816(s[nt], xa[0][jb], bh[jb]);
#pragma unroll
            for (int jb = 0; jb < 4; jb++) mma16816(s[nt], xa[1][jb], bh[jb]);
#pragma unroll
            for (int jb = 0; jb < 4; jb++) mma16816(s[nt], xa[0][jb], bl[jb]);
        }

        // ---- epilogue: cos(sim+phi) -> bf16 split -> A2 frag (m16 k16) ----
        uint32_t ah[4], al[4];
#pragma unroll
        for (int nt = 0; nt < 2; nt++) {
            int cb = cc * 64 + qt * 16 + nt * 8 + (lane & 3) * 2;
            float p0 = sphi[cb], p1 = sphi[cb + 1];
            float v0 = __cosf(s[nt][0] + p0);
            float v1 = __cosf(s[nt][1] + p1);
            float v2 = __cosf(s[nt][2] + p0);
            float v3 = __cosf(s[nt][3] + p1);
            float h0 = __bfloat162float(__float2bfloat16_rn(v0));
            float h1 = __bfloat162float(__float2bfloat16_rn(v1));
            float h2 = __bfloat162float(__float2bfloat16_rn(v2));
            float h3 = __bfloat162float(__float2bfloat16_rn(v3));
            int o = nt * 2;
            ah[o]     = pack_bf2(v0, v1);
            ah[o + 1] = pack_bf2(v2, v3);
            al[o]     = pack_bf2(v0 - h0, v1 - h1);
            al[o + 1] = pack_bf2(v2 - h2, v3 - h3);
        }

        // ---- GEMM2: f += coeff . mat, K=16 (quarter), n=64 ----
#pragma unroll
        for (int it2 = 0; it2 < 4; it2++) {
            // x4t: b-rows qt*16+(lane&15), two n8 blocks it2*16 + (lane>>4)*8
            uint32_t base = mb + (uint32_t)(qt * 16 + (lane & 15)) * ROWB
                          + (uint32_t)(it2 * 16 + ((lane >> 4) & 1) * 8) * 2;
            uint32_t rh[4], rl[4];
            ldsm_x4t(rh, base);          // hi
            ldsm_x4t(rl, base + 128);    // lo
            uint32_t bhA[2] = {rh[0], rh[1]}, bhB[2] = {rh[2], rh[3]};
            uint32_t blA[2] = {rl[0], rl[1]}, blB[2] = {rl[2], rl[3]};
            float* fA = f[it2 * 2];
            float* fB = f[it2 * 2 + 1];
            mma16816(fA, ah, bhA);  mma16816(fB, ah, bhB);
            mma16816(fA, al, bhA);  mma16816(fB, al, bhB);
            mma16816(fA, ah, blA);  mma16816(fB, ah, blB);
        }

        __syncthreads();
        if (cc + 2 < 16) pf_chunk(sb, cc + 2, cc & 1, tid);
        asm volatile("cp.async.commit_group;");
    }

    // ---- combine 4 b-quarter partials per row-group via smem ----
    float* part = (float*)(smem + QBUF(0));   // 8 warps x 16 x 66 f32 = 33792 B
    {
        float* pw = part + w * (16 * 66);
        int r = lane >> 2, cbase = (lane & 3) * 2;
#pragma unroll
        for (int it = 0; it < 8; it++) {
            int col = it * 8 + cbase;
            *(float2*)&pw[r * 66 + col]       = make_float2(f[it][0], f[it][1]);
            *(float2*)&pw[(r + 8) * 66 + col] = make_float2(f[it][2], f[it][3]);
        }
    }
    __syncthreads();
#pragma unroll
    for (int k = 0; k < 2; k++) {
        int e = tid + k * 256;                 // 512 float4s
        int row = e >> 4, c4 = (e & 15) * 4;
        int org = row >> 4, rr = row & 15;
        const float* p0 = part + (org * 4 + 0) * (16 * 66) + rr * 66 + c4;
        const float* p1 = part + (org * 4 + 1) * (16 * 66) + rr * 66 + c4;
        const float* p2 = part + (org * 4 + 2) * (16 * 66) + rr * 66 + c4;
        const float* p3 = part + (org * 4 + 3) * (16 * 66) + rr * 66 + c4;
        float4 o;
        o.x = p0[0] + p1[0] + p2[0] + p3[0];
        o.y = p0[1] + p1[1] + p2[1] + p3[1];
        o.z = p0[2] + p1[2] + p2[2] + p3[2];
        o.w = p0[3] + p1[3] + p2[3] + p3[3];
        *(float4*)&out[(row0 + row) * 64 + c4] = o;
    }
}

extern "C" void kernel_launch(void* const* d_in, const int* in_sizes, int n_in,
                              void* d_out, int out_size) {
    // inputs: 0=t(1), 1=x(8192*64), 2=epsilon(2048*64), 3=lam(64), 4=eta(1), 5=w(4096)
    const float* x   = (const float*)d_in[1];
    const float* eps = (const float*)d_in[2];
    const float* lam = (const float*)d_in[3];
    const float* eta = (const float*)d_in[4];
    const float* w   = (const float*)d_in[5];
    float* out = (float*)d_out;

    ssgp_prep<<<256, 256>>>(eps, lam, eta, w);

    cudaFuncSetAttribute(ssgp_hmma, cudaFuncAttributeMaxDynamicSharedMemorySize,
                         SMEM_BYTES);
    ssgp_hmma<<<256, 256, SMEM_BYTES>>>(x, out);
}

// round 14
// speedup vs baseline: 1.0749x; 1.0749x over previous
#include <cuda_runtime.h>
#include <cuda_bf16.h>
#include <cstdint>

// ============================================================================
// SSGP folded: f[n,i] = sum_{b<1024} cos(sim[n,b]+phi_b) * mat[b,i]
// mma.sync.m16n8k16 bf16, split precision (drop lo*lo).
// 64-row CTAs, grid 128, 2 CTA/SM. Two warp-groups per CTA process
// independent chunk streams (even/odd 32-basis chunks) with their own
// barriers+buffers so MUFU bursts overlap the other group's tensor work.
// ============================================================================

__device__ float g_phi[1024];
__device__ __nv_bfloat16 g_qs[32][32][128];  // [chunk][b][ qh(64) | ql(64) ]
__device__ __nv_bfloat16 g_ms[32][32][128];  // [chunk][b][ mh(64) | ml(64) ]

// ---------------- prep ----------------
__global__ void ssgp_prep(const float* __restrict__ eps,
                          const float* __restrict__ lam,
                          const float* __restrict__ eta,
                          const float* __restrict__ w) {
    int idx = blockIdx.x * blockDim.x + threadIdx.x;  // 65536
    int b = idx >> 6, j = idx & 63;
    int ch = b >> 5, bp = b & 31;
    float S = w[b] + w[b + 1024];
    float C = w[2048 + b] - w[3072 + b];
    float R = sqrtf(S * S + C * C);
    if (j == 0) g_phi[b] = atan2f(S, C);

    float e2 = eta[0] * eta[0];
    float q = eps[b * 64 + j] / lam[j];
    __nv_bfloat16 qh = __float2bfloat16_rn(q);
    __nv_bfloat16 ql = __float2bfloat16_rn(q - __bfloat162float(qh));
    g_qs[ch][bp][j]      = qh;
    g_qs[ch][bp][64 + j] = ql;

    float m;
    if (j < 32) m = R * (eps[b * 64 + j + 32] / lam[j + 32]);
    else        m = -R * (eps[b * 64 + j - 32] / lam[j - 32] + e2 * q);
    __nv_bfloat16 mh = __float2bfloat16_rn(m);
    __nv_bfloat16 ml = __float2bfloat16_rn(m - __bfloat162float(mh));
    g_ms[ch][bp][j]      = mh;
    g_ms[ch][bp][64 + j] = ml;
}

// ---------------- asm helpers ----------------
__device__ __forceinline__ uint32_t smem_u32(const void* p) {
    uint32_t a;
    asm("{ .reg .u64 t; cvta.to.shared.u64 t, %1; cvt.u32.u64 %0, t; }" : "=r"(a) : "l"(p));
    return a;
}
__device__ __forceinline__ void mma16816(float* d, const uint32_t* a, const uint32_t* b) {
    asm volatile(
        "mma.sync.aligned.m16n8k16.row.col.f32.bf16.bf16.f32 "
        "{%0,%1,%2,%3}, {%4,%5,%6,%7}, {%8,%9}, {%0,%1,%2,%3};"
        : "+f"(d[0]), "+f"(d[1]), "+f"(d[2]), "+f"(d[3])
        : "r"(a[0]), "r"(a[1]), "r"(a[2]), "r"(a[3]), "r"(b[0]), "r"(b[1]));
}
__device__ __forceinline__ void ldsm_x4(uint32_t* r, uint32_t addr) {
    asm volatile("ldmatrix.sync.aligned.m8n8.x4.shared.b16 {%0,%1,%2,%3}, [%4];"
                 : "=r"(r[0]), "=r"(r[1]), "=r"(r[2]), "=r"(r[3]) : "r"(addr));
}
__device__ __forceinline__ void ldsm_x4t(uint32_t* r, uint32_t addr) {
    asm volatile("ldmatrix.sync.aligned.m8n8.x4.trans.shared.b16 {%0,%1,%2,%3}, [%4];"
                 : "=r"(r[0]), "=r"(r[1]), "=r"(r[2]), "=r"(r[3]) : "r"(addr));
}
__device__ __forceinline__ void cpa16(uint32_t s, const void* g) {
    asm volatile("cp.async.cg.shared.global [%0], [%1], 16;" :: "r"(s), "l"(g));
}
__device__ __forceinline__ uint32_t pack_bf2(float lo, float hi) {
    __nv_bfloat162 v(__float2bfloat16_rn(lo), __float2bfloat16_rn(hi));
    return *(uint32_t*)&v;
}

// ---------------- smem layout (per CTA: 91136 B) ----------------
#define ROWB 272                  // 128 bf16 + 16B pad
#define SX_OFF 0                  // x tile: 64 rows x ROWB = 17408
#define TBL 8704                  // one 32-row chunk table
#define QBUF(g,d) (17408 + ((g)*2+(d)) * TBL)   // 4 bufs -> ends 52224
#define MBUF(g,d) (52224 + ((g)*2+(d)) * TBL)   // 4 bufs -> ends 87040
#define PHI_OFF 87040             // 1024 f32
#define SMEM_BYTES 91136

__device__ __forceinline__ void pf_chunk(uint32_t sb, int gc, int grp, int d, int t128) {
    uint32_t qdst = sb + QBUF(grp, d);
    uint32_t mdst = sb + MBUF(grp, d);
    const char* qsrc = (const char*)g_qs[gc];
    const char* msrc = (const char*)g_ms[gc];
    // 32 rows x 256 data bytes = 512 x 16B units exactly (stride ROWB in smem)
#pragma unroll
    for (int r = 0; r < 4; r++) {
        int e = t128 + r * 128;               // 0..511
        uint32_t off = (uint32_t)(e >> 4) * ROWB + (uint32_t)(e & 15) * 16;
        cpa16(qdst + off, qsrc + e * 16);
        cpa16(mdst + off, msrc + e * 16);
    }
}

// ---------------- main ----------------
__global__ void __launch_bounds__(256, 2)
ssgp_hmma(const float* __restrict__ x, float* __restrict__ out) {
    extern __shared__ char smem[];
    const uint32_t sb = smem_u32(smem);
    const int tid = threadIdx.x, lane = tid & 31, w = tid >> 5;
    const int grp = w >> 2, rg = w & 3;       // group (chunk parity), 16-row group
    const int t128 = tid & 127;
    const int row0 = blockIdx.x * 64;

    // prefetch phi + this group's first two chunks
    cpa16(sb + PHI_OFF + tid * 16, (const char*)g_phi + tid * 16);
    pf_chunk(sb, grp, grp, 0, t128);
    asm volatile("cp.async.commit_group;");
    pf_chunk(sb, grp + 2, grp, 1, t128);
    asm volatile("cp.async.commit_group;");

    // stage x tile: 64 rows x [xh(64)|xl(64)] bf16
#pragma unroll
    for (int k = 0; k < 4; k++) {
        int e = tid + k * 256;                 // 1024 float4s
        int row = e >> 4, c4 = e & 15;
        float4 v = *(const float4*)&x[(row0 + row) * 64 + c4 * 4];
        float vh[4] = {v.x, v.y, v.z, v.w};
        uint32_t hp[2], lp[2];
#pragma unroll
        for (int p = 0; p < 2; p++) {
            float a = vh[2 * p], b = vh[2 * p + 1];
            float ah_ = __bfloat162float(__float2bfloat16_rn(a));
            float bh_ = __bfloat162float(__float2bfloat16_rn(b));
            hp[p] = pack_bf2(a, b);
            lp[p] = pack_bf2(a - ah_, b - bh_);
        }
        char* rp = smem + SX_OFF + row * ROWB;
        *(uint2*)(rp + c4 * 8)       = make_uint2(hp[0], hp[1]);
        *(uint2*)(rp + 128 + c4 * 8) = make_uint2(lp[0], lp[1]);
    }
    __syncthreads();

    // persistent x A-fragments [hi/lo][jb][4] for rows rg*16..+15
    uint32_t xa[2][4][4];
#pragma unroll
    for (int s = 0; s < 2; s++)
#pragma unroll
        for (int jb = 0; jb < 4; jb++) {
            uint32_t addr = sb + SX_OFF + (uint32_t)(rg * 16 + (lane & 15)) * ROWB
                          + (uint32_t)(s * 64 + jb * 16 + ((lane >> 4) & 1) * 8) * 2;
            ldsm_x4(xa[s][jb], addr);
        }

    float f[8][4];
#pragma unroll
    for (int it = 0; it < 8; it++)
#pragma unroll
        for (int r = 0; r < 4; r++) f[it][r] = 0.f;

    const float* sphi = (const float*)(smem + PHI_OFF);

    for (int k = 0; k < 16; ++k) {
        const int gc = grp + 2 * k;
        asm volatile("cp.async.wait_group 1;" ::: "memory");
        asm volatile("bar.sync %0, 128;" :: "r"(1 + grp) : "memory");
        const uint32_t qb = sb + QBUF(grp, k & 1);
        const uint32_t mb = sb + MBUF(grp, k & 1);

        // ---- GEMM1: sim[16 x 32] = x . q^T, K=192 split; nt in pairs ----
        float s[4][4];
#pragma unroll
        for (int np = 0; np < 2; np++) {
            uint32_t bh[2][4][2], bl[2][4][2];
#pragma unroll
            for (int p = 0; p < 2; p++) {
                int nt = np * 2 + p;
                uint32_t base = qb + (uint32_t)(nt * 8 + (lane & 7)) * ROWB
                              + (uint32_t)((lane >> 3) * 8) * 2;
                uint32_t r[4];
                ldsm_x4(r, base);              // hi k 0..31
                bh[p][0][0] = r[0]; bh[p][0][1] = r[1];
                bh[p][1][0] = r[2]; bh[p][1][1] = r[3];
                ldsm_x4(r, base + 64);         // hi k 32..63
                bh[p][2][0] = r[0]; bh[p][2][1] = r[1];
                bh[p][3][0] = r[2]; bh[p][3][1] = r[3];
                ldsm_x4(r, base + 128);        // lo k 0..31
                bl[p][0][0] = r[0]; bl[p][0][1] = r[1];
                bl[p][1][0] = r[2]; bl[p][1][1] = r[3];
                ldsm_x4(r, base + 192);        // lo k 32..63
                bl[p][2][0] = r[0]; bl[p][2][1] = r[1];
                bl[p][3][0] = r[2]; bl[p][3][1] = r[3];
            }
            float* s0 = s[np * 2];
            float* s1 = s[np * 2 + 1];
#pragma unroll
            for (int r4 = 0; r4 < 4; r4++) { s0[r4] = 0.f; s1[r4] = 0.f; }
#pragma unroll
            for (int jb = 0; jb < 4; jb++) {
                mma16816(s0, xa[0][jb], bh[0][jb]);
                mma16816(s1, xa[0][jb], bh[1][jb]);
            }
#pragma unroll
            for (int jb = 0; jb < 4; jb++) {
                mma16816(s0, xa[1][jb], bh[0][jb]);
                mma16816(s1, xa[1][jb], bh[1][jb]);
            }
#pragma unroll
            for (int jb = 0; jb < 4; jb++) {
                mma16816(s0, xa[0][jb], bl[0][jb]);
                mma16816(s1, xa[0][jb], bl[1][jb]);
            }
        }

        // ---- epilogue: cos(sim+phi) -> bf16 split -> A2 frags (m16k32) ----
        uint32_t ah[2][4], al[2][4];
#pragma unroll
        for (int nt = 0; nt < 4; nt++) {
            int cb = gc * 32 + nt * 8 + (lane & 3) * 2;
            float p0 = sphi[cb], p1 = sphi[cb + 1];
            float v0 = __cosf(s[nt][0] + p0);
            float v1 = __cosf(s[nt][1] + p1);
            float v2 = __cosf(s[nt][2] + p0);
            float v3 = __cosf(s[nt][3] + p1);
            float h0 = __bfloat162float(__float2bfloat16_rn(v0));
            float h1 = __bfloat162float(__float2bfloat16_rn(v1));
            float h2 = __bfloat162float(__float2bfloat16_rn(v2));
            float h3 = __bfloat162float(__float2bfloat16_rn(v3));
            int t = nt >> 1, o = (nt & 1) * 2;
            ah[t][o]     = pack_bf2(v0, v1);
            ah[t][o + 1] = pack_bf2(v2, v3);
            al[t][o]     = pack_bf2(v0 - h0, v1 - h1);
            al[t][o + 1] = pack_bf2(v2 - h2, v3 - h3);
        }

        // ---- GEMM2: f += coeff . mat, K=32 split, n=64 ----
#pragma unroll
        for (int it2 = 0; it2 < 4; it2++) {
            uint32_t base = mb + (uint32_t)(lane & 15) * ROWB
                          + (uint32_t)(it2 * 16 + ((lane >> 4) & 1) * 8) * 2;
            uint32_t rh0[4], rh1[4], rl0[4], rl1[4];
            ldsm_x4t(rh0, base);                     // kb0 hi
            ldsm_x4t(rh1, base + 16u * ROWB);        // kb1 hi
            ldsm_x4t(rl0, base + 128);               // kb0 lo
            ldsm_x4t(rl1, base + 16u * ROWB + 128);  // kb1 lo
            uint32_t bhA0[2] = {rh0[0], rh0[1]}, bhB0[2] = {rh0[2], rh0[3]};
            uint32_t bhA1[2] = {rh1[0], rh1[1]}, bhB1[2] = {rh1[2], rh1[3]};
            uint32_t blA0[2] = {rl0[0], rl0[1]}, blB0[2] = {rl0[2], rl0[3]};
            uint32_t blA1[2] = {rl1[0], rl1[1]}, blB1[2] = {rl1[2], rl1[3]};
            float* fA = f[it2 * 2];
            float* fB = f[it2 * 2 + 1];
            mma16816(fA, ah[0], bhA0);  mma16816(fB, ah[0], bhB0);
            mma16816(fA, ah[1], bhA1);  mma16816(fB, ah[1], bhB1);
            mma16816(fA, al[0], bhA0);  mma16816(fB, al[0], bhB0);
            mma16816(fA, al[1], bhA1);  mma16816(fB, al[1], bhB1);
            mma16816(fA, ah[0], blA0);  mma16816(fB, ah[0], blB0);
            mma16816(fA, ah[1], blA1);  mma16816(fB, ah[1], blB1);
        }

        asm volatile("bar.sync %0, 128;" :: "r"(1 + grp) : "memory");
        if (k + 2 < 16) pf_chunk(sb, gc + 4, grp, k & 1, t128);
        asm volatile("cp.async.commit_group;");
    }

    // ---- combine the 2 group-partials per row via smem ----
    __syncthreads();                         // both groups done with tables
    float* part = (float*)(smem + QBUF(0, 0));   // 128 rows x 68 f32 = 34816 B
    {
        int pr = grp * 64 + rg * 16 + (lane >> 2);
        int cbase = (lane & 3) * 2;
#pragma unroll
        for (int it = 0; it < 8; it++) {
            int col = it * 8 + cbase;
            *(float2*)&part[pr * 68 + col]       = make_float2(f[it][0], f[it][1]);
            *(float2*)&part[(pr + 8) * 68 + col] = make_float2(f[it][2], f[it][3]);
        }
    }
    __syncthreads();
#pragma unroll
    for (int k = 0; k < 4; k++) {
        int e = tid + k * 256;                 // 1024 float4s
        int row = e >> 4, c4 = (e & 15) * 4;
        float4 a = *(const float4*)&part[row * 68 + c4];
        float4 b = *(const float4*)&part[(64 + row) * 68 + c4];
        float4 o;
        o.x = a.x + b.x; o.y = a.y + b.y; o.z = a.z + b.z; o.w = a.w + b.w;
        *(float4*)&out[(row0 + row) * 64 + c4] = o;
    }
}

extern "C" void kernel_launch(void* const* d_in, const int* in_sizes, int n_in,
                              void* d_out, int out_size) {
    // inputs: 0=t(1), 1=x(8192*64), 2=epsilon(2048*64), 3=lam(64), 4=eta(1), 5=w(4096)
    const float* x   = (const float*)d_in[1];
    const float* eps = (const float*)d_in[2];
    const float* lam = (const float*)d_in[3];
    const float* eta = (const float*)d_in[4];
    const float* w   = (const float*)d_in[5];
    float* out = (float*)d_out;

    ssgp_prep<<<256, 256>>>(eps, lam, eta, w);

    cudaFuncSetAttribute(ssgp_hmma, cudaFuncAttributeMaxDynamicSharedMemorySize,
                         SMEM_BYTES);
    ssgp_hmma<<<128, 256, SMEM_BYTES>>>(x, out);
}

// round 15
// speedup vs baseline: 1.1491x; 1.0691x over previous
#include <cuda_runtime.h>
#include <cuda_bf16.h>
#include <cstdint>

// ============================================================================
// SSGP folded: f[n,i] = sum_{b<1024} cos(sim[n,b]+phi_b) * mat[b,i]
// mma.sync.m16n8k16 bf16, split precision (drop lo*lo).
// 64-row CTAs, grid 128, 512 threads: FOUR warp-groups per CTA on
// independent chunk streams (stride-4) with private barriers+buffers ->
// 4 warps/SMSP with drifting phases; MUFU overlaps other groups' HMMA.
// ============================================================================

__device__ float g_phi[1024];
__device__ __nv_bfloat16 g_qs[32][32][128];  // [chunk][b][ qh(64) | ql(64) ]
__device__ __nv_bfloat16 g_ms[32][32][128];  // [chunk][b][ mh(64) | ml(64) ]

// ---------------- prep ----------------
__global__ void ssgp_prep(const float* __restrict__ eps,
                          const float* __restrict__ lam,
                          const float* __restrict__ eta,
                          const float* __restrict__ w) {
    int idx = blockIdx.x * blockDim.x + threadIdx.x;  // 65536
    int b = idx >> 6, j = idx & 63;
    int ch = b >> 5, bp = b & 31;
    float S = w[b] + w[b + 1024];
    float C = w[2048 + b] - w[3072 + b];
    float R = sqrtf(S * S + C * C);
    if (j == 0) g_phi[b] = atan2f(S, C);

    float e2 = eta[0] * eta[0];
    float q = eps[b * 64 + j] / lam[j];
    __nv_bfloat16 qh = __float2bfloat16_rn(q);
    __nv_bfloat16 ql = __float2bfloat16_rn(q - __bfloat162float(qh));
    g_qs[ch][bp][j]      = qh;
    g_qs[ch][bp][64 + j] = ql;

    float m;
    if (j < 32) m = R * (eps[b * 64 + j + 32] / lam[j + 32]);
    else        m = -R * (eps[b * 64 + j - 32] / lam[j - 32] + e2 * q);
    __nv_bfloat16 mh = __float2bfloat16_rn(m);
    __nv_bfloat16 ml = __float2bfloat16_rn(m - __bfloat162float(mh));
    g_ms[ch][bp][j]      = mh;
    g_ms[ch][bp][64 + j] = ml;
}

// ---------------- asm helpers ----------------
__device__ __forceinline__ uint32_t smem_u32(const void* p) {
    uint32_t a;
    asm("{ .reg .u64 t; cvta.to.shared.u64 t, %1; cvt.u32.u64 %0, t; }" : "=r"(a) : "l"(p));
    return a;
}
__device__ __forceinline__ void mma16816(float* d, const uint32_t* a, const uint32_t* b) {
    asm volatile(
        "mma.sync.aligned.m16n8k16.row.col.f32.bf16.bf16.f32 "
        "{%0,%1,%2,%3}, {%4,%5,%6,%7}, {%8,%9}, {%0,%1,%2,%3};"
        : "+f"(d[0]), "+f"(d[1]), "+f"(d[2]), "+f"(d[3])
        : "r"(a[0]), "r"(a[1]), "r"(a[2]), "r"(a[3]), "r"(b[0]), "r"(b[1]));
}
__device__ __forceinline__ void ldsm_x4(uint32_t* r, uint32_t addr) {
    asm volatile("ldmatrix.sync.aligned.m8n8.x4.shared.b16 {%0,%1,%2,%3}, [%4];"
                 : "=r"(r[0]), "=r"(r[1]), "=r"(r[2]), "=r"(r[3]) : "r"(addr));
}
__device__ __forceinline__ void ldsm_x4t(uint32_t* r, uint32_t addr) {
    asm volatile("ldmatrix.sync.aligned.m8n8.x4.trans.shared.b16 {%0,%1,%2,%3}, [%4];"
                 : "=r"(r[0]), "=r"(r[1]), "=r"(r[2]), "=r"(r[3]) : "r"(addr));
}
__device__ __forceinline__ void cpa16(uint32_t s, const void* g) {
    asm volatile("cp.async.cg.shared.global [%0], [%1], 16;" :: "r"(s), "l"(g));
}
__device__ __forceinline__ uint32_t pack_bf2(float lo, float hi) {
    __nv_bfloat162 v(__float2bfloat16_rn(lo), __float2bfloat16_rn(hi));
    return *(uint32_t*)&v;
}

// ---------------- smem layout (per CTA: 160768 B) ----------------
#define ROWB 272                  // 128 bf16 + 16B pad
#define SX_OFF 0                  // x tile: 64 rows x ROWB = 17408
#define TBL 8704                  // one 32-row chunk table
#define QBUF(g,d) (17408 + ((g)*2+(d)) * TBL)   // 8 bufs -> ends 87040
#define MBUF(g,d) (87040 + ((g)*2+(d)) * TBL)   // 8 bufs -> ends 156672
#define PHI_OFF 156672            // 1024 f32
#define SMEM_BYTES 160768

__device__ __forceinline__ void pf_chunk(uint32_t sb, int gc, int grp, int d, int t128) {
    uint32_t qdst = sb + QBUF(grp, d);
    uint32_t mdst = sb + MBUF(grp, d);
    const char* qsrc = (const char*)g_qs[gc];
    const char* msrc = (const char*)g_ms[gc];
    // 32 rows x 256 data bytes = 512 x 16B units exactly
#pragma unroll
    for (int r = 0; r < 4; r++) {
        int e = t128 + r * 128;               // 0..511
        uint32_t off = (uint32_t)(e >> 4) * ROWB + (uint32_t)(e & 15) * 16;
        cpa16(qdst + off, qsrc + e * 16);
        cpa16(mdst + off, msrc + e * 16);
    }
}

// ---------------- main ----------------
__global__ void __launch_bounds__(512, 1)
ssgp_hmma(const float* __restrict__ x, float* __restrict__ out) {
    extern __shared__ char smem[];
    const uint32_t sb = smem_u32(smem);
    const int tid = threadIdx.x, lane = tid & 31, w = tid >> 5;
    const int grp = w >> 2, rg = w & 3;       // group 0..3, 16-row group 0..3
    const int t128 = tid & 127;               // thread-in-group
    const int row0 = blockIdx.x * 64;

    // prefetch phi + this group's first two chunks (gc = grp, grp+4)
    if (tid < 256) cpa16(sb + PHI_OFF + tid * 16, (const char*)g_phi + tid * 16);
    pf_chunk(sb, grp, grp, 0, t128);
    asm volatile("cp.async.commit_group;");
    pf_chunk(sb, grp + 4, grp, 1, t128);
    asm volatile("cp.async.commit_group;");

    // stage x tile: 64 rows x [xh(64)|xl(64)] bf16
#pragma unroll
    for (int k = 0; k < 2; k++) {
        int e = tid + k * 512;                 // 1024 float4s
        int row = e >> 4, c4 = e & 15;
        float4 v = *(const float4*)&x[(row0 + row) * 64 + c4 * 4];
        float vh[4] = {v.x, v.y, v.z, v.w};
        uint32_t hp[2], lp[2];
#pragma unroll
        for (int p = 0; p < 2; p++) {
            float a = vh[2 * p], b = vh[2 * p + 1];
            float ah_ = __bfloat162float(__float2bfloat16_rn(a));
            float bh_ = __bfloat162float(__float2bfloat16_rn(b));
            hp[p] = pack_bf2(a, b);
            lp[p] = pack_bf2(a - ah_, b - bh_);
        }
        char* rp = smem + SX_OFF + row * ROWB;
        *(uint2*)(rp + c4 * 8)       = make_uint2(hp[0], hp[1]);
        *(uint2*)(rp + 128 + c4 * 8) = make_uint2(lp[0], lp[1]);
    }
    __syncthreads();

    // persistent x A-fragments [hi/lo][jb][4] for rows rg*16..+15
    uint32_t xa[2][4][4];
#pragma unroll
    for (int s = 0; s < 2; s++)
#pragma unroll
        for (int jb = 0; jb < 4; jb++) {
            uint32_t addr = sb + SX_OFF + (uint32_t)(rg * 16 + (lane & 15)) * ROWB
                          + (uint32_t)(s * 64 + jb * 16 + ((lane >> 4) & 1) * 8) * 2;
            ldsm_x4(xa[s][jb], addr);
        }

    float f[8][4];
#pragma unroll
    for (int it = 0; it < 8; it++)
#pragma unroll
        for (int r = 0; r < 4; r++) f[it][r] = 0.f;

    const float* sphi = (const float*)(smem + PHI_OFF);

    for (int k = 0; k < 8; ++k) {
        const int gc = grp + 4 * k;
        asm volatile("cp.async.wait_group 1;" ::: "memory");
        asm volatile("bar.sync %0, 128;" :: "r"(1 + grp) : "memory");
        const uint32_t qb = sb + QBUF(grp, k & 1);
        const uint32_t mb = sb + MBUF(grp, k & 1);

        // ---- GEMM1: sim[16 x 32] = x . q^T, K=192 split; nt in pairs ----
        float s[4][4];
#pragma unroll
        for (int np = 0; np < 2; np++) {
            uint32_t bh[2][4][2], bl[2][4][2];
#pragma unroll
            for (int p = 0; p < 2; p++) {
                int nt = np * 2 + p;
                uint32_t base = qb + (uint32_t)(nt * 8 + (lane & 7)) * ROWB
                              + (uint32_t)((lane >> 3) * 8) * 2;
                uint32_t r[4];
                ldsm_x4(r, base);              // hi k 0..31
                bh[p][0][0] = r[0]; bh[p][0][1] = r[1];
                bh[p][1][0] = r[2]; bh[p][1][1] = r[3];
                ldsm_x4(r, base + 64);         // hi k 32..63
                bh[p][2][0] = r[0]; bh[p][2][1] = r[1];
                bh[p][3][0] = r[2]; bh[p][3][1] = r[3];
                ldsm_x4(r, base + 128);        // lo k 0..31
                bl[p][0][0] = r[0]; bl[p][0][1] = r[1];
                bl[p][1][0] = r[2]; bl[p][1][1] = r[3];
                ldsm_x4(r, base + 192);        // lo k 32..63
                bl[p][2][0] = r[0]; bl[p][2][1] = r[1];
                bl[p][3][0] = r[2]; bl[p][3][1] = r[3];
            }
            float* s0 = s[np * 2];
            float* s1 = s[np * 2 + 1];
#pragma unroll
            for (int r4 = 0; r4 < 4; r4++) { s0[r4] = 0.f; s1[r4] = 0.f; }
#pragma unroll
            for (int jb = 0; jb < 4; jb++) {
                mma16816(s0, xa[0][jb], bh[0][jb]);
                mma16816(s1, xa[0][jb], bh[1][jb]);
            }
#pragma unroll
            for (int jb = 0; jb < 4; jb++) {
                mma16816(s0, xa[1][jb], bh[0][jb]);
                mma16816(s1, xa[1][jb], bh[1][jb]);
            }
#pragma unroll
            for (int jb = 0; jb < 4; jb++) {
                mma16816(s0, xa[0][jb], bl[0][jb]);
                mma16816(s1, xa[0][jb], bl[1][jb]);
            }
        }

        // ---- epilogue: cos(sim+phi) -> bf16 split -> A2 frags (m16k32) ----
        uint32_t ah[2][4], al[2][4];
#pragma unroll
        for (int nt = 0; nt < 4; nt++) {
            int cb = gc * 32 + nt * 8 + (lane & 3) * 2;
            float p0 = sphi[cb], p1 = sphi[cb + 1];
            float v0 = __cosf(s[nt][0] + p0);
            float v1 = __cosf(s[nt][1] + p1);
            float v2 = __cosf(s[nt][2] + p0);
            float v3 = __cosf(s[nt][3] + p1);
            float h0 = __bfloat162float(__float2bfloat16_rn(v0));
            float h1 = __bfloat162float(__float2bfloat16_rn(v1));
            float h2 = __bfloat162float(__float2bfloat16_rn(v2));
            float h3 = __bfloat162float(__float2bfloat16_rn(v3));
            int t = nt >> 1, o = (nt & 1) * 2;
            ah[t][o]     = pack_bf2(v0, v1);
            ah[t][o + 1] = pack_bf2(v2, v3);
            al[t][o]     = pack_bf2(v0 - h0, v1 - h1);
            al[t][o + 1] = pack_bf2(v2 - h2, v3 - h3);
        }

        // ---- GEMM2: f += coeff . mat, K=32 split, n=64 ----
#pragma unroll
        for (int it2 = 0; it2 < 4; it2++) {
            uint32_t base = mb + (uint32_t)(lane & 15) * ROWB
                          + (uint32_t)(it2 * 16 + ((lane >> 4) & 1) * 8) * 2;
            uint32_t rh0[4], rh1[4], rl0[4], rl1[4];
            ldsm_x4t(rh0, base);                     // kb0 hi
            ldsm_x4t(rh1, base + 16u * ROWB);        // kb1 hi
            ldsm_x4t(rl0, base + 128);               // kb0 lo
            ldsm_x4t(rl1, base + 16u * ROWB + 128);  // kb1 lo
            uint32_t bhA0[2] = {rh0[0], rh0[1]}, bhB0[2] = {rh0[2], rh0[3]};
            uint32_t bhA1[2] = {rh1[0], rh1[1]}, bhB1[2] = {rh1[2], rh1[3]};
            uint32_t blA0[2] = {rl0[0], rl0[1]}, blB0[2] = {rl0[2], rl0[3]};
            uint32_t blA1[2] = {rl1[0], rl1[1]}, blB1[2] = {rl1[2], rl1[3]};
            float* fA = f[it2 * 2];
            float* fB = f[it2 * 2 + 1];
            mma16816(fA, ah[0], bhA0);  mma16816(fB, ah[0], bhB0);
            mma16816(fA, ah[1], bhA1);  mma16816(fB, ah[1], bhB1);
            mma16816(fA, al[0], bhA0);  mma16816(fB, al[0], bhB0);
            mma16816(fA, al[1], bhA1);  mma16816(fB, al[1], bhB1);
            mma16816(fA, ah[0], blA0);  mma16816(fB, ah[0], blB0);
            mma16816(fA, ah[1], blA1);  mma16816(fB, ah[1], blB1);
        }

        asm volatile("bar.sync %0, 128;" :: "r"(1 + grp) : "memory");
        if (k + 2 < 8) pf_chunk(sb, gc + 8, grp, k & 1, t128);
        asm volatile("cp.async.commit_group;");
    }

    // ---- combine the 4 group-partials per row via smem ----
    __syncthreads();                         // all groups done with tables
    float* part = (float*)(smem + QBUF(0, 0));   // 256 rows x 68 f32 = 69632 B
    {
        int pr = grp * 64 + rg * 16 + (lane >> 2);
        int cbase = (lane & 3) * 2;
#pragma unroll
        for (int it = 0; it < 8; it++) {
            int col = it * 8 + cbase;
            *(float2*)&part[pr * 68 + col]       = make_float2(f[it][0], f[it][1]);
            *(float2*)&part[(pr + 8) * 68 + col] = make_float2(f[it][2], f[it][3]);
        }
    }
    __syncthreads();
#pragma unroll
    for (int k = 0; k < 2; k++) {
        int e = tid + k * 512;                 // 1024 float4s
        int row = e >> 4, c4 = (e & 15) * 4;
        float4 a = *(const float4*)&part[row * 68 + c4];
        float4 b = *(const float4*)&part[(64 + row) * 68 + c4];
        float4 c = *(const float4*)&part[(128 + row) * 68 + c4];
        float4 d = *(const float4*)&part[(192 + row) * 68 + c4];
        float4 o;
        o.x = a.x + b.x + c.x + d.x;
        o.y = a.y + b.y + c.y + d.y;
        o.z = a.z + b.z + c.z + d.z;
        o.w = a.w + b.w + c.w + d.w;
        *(float4*)&out[(row0 + row) * 64 + c4] = o;
    }
}

extern "C" void kernel_launch(void* const* d_in, const int* in_sizes, int n_in,
                              void* d_out, int out_size) {
    // inputs: 0=t(1), 1=x(8192*64), 2=epsilon(2048*64), 3=lam(64), 4=eta(1), 5=w(4096)
    const float* x   = (const float*)d_in[1];
    const float* eps = (const float*)d_in[2];
    const float* lam = (const float*)d_in[3];
    const float* eta = (const float*)d_in[4];
    const float* w   = (const float*)d_in[5];
    float* out = (float*)d_out;

    ssgp_prep<<<256, 256>>>(eps, lam, eta, w);

    cudaFuncSetAttribute(ssgp_hmma, cudaFuncAttributeMaxDynamicSharedMemorySize,
                         SMEM_BYTES);
    ssgp_hmma<<<128, 512, SMEM_BYTES>>>(x, out);
}